// round 15
// baseline (speedup 1.0000x reference)
#include <cuda_runtime.h>
#include <cuda_bf16.h>
#include <mma.h>
#include <math.h>
#include <stdint.h>

using namespace nvcuda;

#define B_SZ    8
#define L_SEQ   1024
#define ENC_IN  32
#define D_MODEL 256
#define D_INNER 512
#define D_STATE 16
#define D_CONV  4
#define DT_RANK 16
#define N_LAYERS 2
#define D_FF    1024
#define MROWS   (B_SZ * L_SEQ)   // 8192
#define XDBL_W  (DT_RANK + 2 * D_STATE)   // 48
#define KSPL    4

typedef unsigned long long ull;
typedef unsigned int u32;

// ---------------- scratch (static device globals; no allocs allowed) -------
__device__ float g_h   [MROWS * D_MODEL];
__device__ float g_xz  [MROWS * 2 * D_INNER];
__device__ float g_xc  [MROWS * D_INNER];
__device__ float g_xdbl[MROWS * XDBL_W];
__device__ float g_part[KSPL * MROWS * XDBL_W];
__device__ float g_dt  [MROWS * D_INNER];
__device__ float g_y   [MROWS * D_INNER];
__device__ float g_fc  [B_SZ * D_FF];

__device__ __nv_bfloat16 g_h3 [MROWS * 3 * D_MODEL];
__device__ __nv_bfloat16 g_y3 [MROWS * 3 * D_INNER];
__device__ __nv_bfloat16 g_w3a[N_LAYERS * 2 * D_INNER * 3 * D_MODEL];
__device__ __nv_bfloat16 g_w3b[N_LAYERS * D_MODEL * 3 * D_INNER];

// ---------------- packed f32x2 helpers -------------------------------------
__device__ __forceinline__ ull pk2(float x, float y) {
    ull r;
    asm("mov.b64 %0, {%1, %2};" : "=l"(r) : "f"(x), "f"(y));
    return r;
}
__device__ __forceinline__ void fma2(ull& c, ull a, ull b) {
    asm("fma.rn.f32x2 %0, %1, %2, %0;" : "+l"(c) : "l"(a), "l"(b));
}
__device__ __forceinline__ float2 upk2(ull v) {
    float2 r;
    asm("mov.b64 {%0, %1}, %2;" : "=f"(r.x), "=f"(r.y) : "l"(v));
    return r;
}
__device__ __forceinline__ u32 pack_bf2(__nv_bfloat16 a, __nv_bfloat16 b) {
    __nv_bfloat162 t = __halves2bfloat162(a, b);
    return *(u32*)&t;
}
__device__ __forceinline__ u32 cvta_smem(const void* p) {
    u32 a;
    asm("{ .reg .u64 t; cvta.to.shared.u64 t, %1; cvt.u32.u64 %0, t; }"
        : "=r"(a) : "l"(p));
    return a;
}
__device__ __forceinline__ void cpa16(u32 s, const void* g) {
    asm volatile("cp.async.cg.shared.global [%0], [%1], 16;"
                 :: "r"(s), "l"(g));
}
#define CPA_COMMIT() asm volatile("cp.async.commit_group;" ::: "memory")
#define CPA_WAIT2()  asm volatile("cp.async.wait_group 2;" ::: "memory")

// ---------------------------------------------------------------------------
// hi/lo split for weights: mode 1 row layout [hi | lo | hi].
// ---------------------------------------------------------------------------
__global__ void split3_kernel(const float* __restrict__ in,
                              __nv_bfloat16* __restrict__ out,
                              int total, int K, int mode)
{
    int idx = blockIdx.x * blockDim.x + threadIdx.x;
    if (idx >= total) return;
    const float x = in[idx];
    const __nv_bfloat16 hi = __float2bfloat16(x);
    const __nv_bfloat16 lo = __float2bfloat16(x - __bfloat162float(hi));
    const int r = idx / K;
    const int k = idx - r * K;
    __nv_bfloat16* o = out + (size_t)r * 3 * K + k;
    o[0] = hi;
    o[K] = mode ? lo : hi;
    o[2 * K] = mode ? hi : lo;
}

// ---------------------------------------------------------------------------
// Fused z-gate + hi/lo split (A-mode [hi|hi|lo]) for y -> y3; 2 d per thread.
// ---------------------------------------------------------------------------
__global__ void gate_split3_kernel(const float* __restrict__ y,
                                   const float* __restrict__ xz,
                                   __nv_bfloat16* __restrict__ out)
{
    int idx = blockIdx.x * blockDim.x + threadIdx.x;       // pair index
    if (idx >= MROWS * D_INNER / 2) return;
    const int r = idx >> 8;                                // 256 pairs/row
    const int d = (idx & 255) * 2;
    const float2 zv = *(const float2*)&xz[(size_t)r * (2 * D_INNER) + D_INNER + d];
    const float2 yv = *(const float2*)&y[(size_t)r * D_INNER + d];
    const float x0 = yv.x * (zv.x / (1.f + __expf(-zv.x)));
    const float x1 = yv.y * (zv.y / (1.f + __expf(-zv.y)));
    const __nv_bfloat16 h0 = __float2bfloat16(x0);
    const __nv_bfloat16 l0 = __float2bfloat16(x0 - __bfloat162float(h0));
    const __nv_bfloat16 h1 = __float2bfloat16(x1);
    const __nv_bfloat16 l1 = __float2bfloat16(x1 - __bfloat162float(h1));
    __nv_bfloat16* o = out + (size_t)r * 3 * D_INNER + d;
    const u32 hp = pack_bf2(h0, h1);
    *(u32*)&o[0] = hp;
    *(u32*)&o[D_INNER] = hp;
    *(u32*)&o[2 * D_INNER] = pack_bf2(l0, l1);
}

// ---------------------------------------------------------------------------
// wmma bf16 GEMM with 4-stage cp.async pipeline (KD=16 per stage).
//   C[M,N] = A3[M,K3] @ W3[N,K3]^T
// EMIT3: also write C3[M,3N] = [hi|hi|lo] split of C.
// ---------------------------------------------------------------------------
template<int BM, int BN, int WM, int WN, int TH, int EMIT3>
__global__ void __launch_bounds__(TH) wmma_gemm(
    const __nv_bfloat16* __restrict__ A, const __nv_bfloat16* __restrict__ W,
    float* __restrict__ C, __nv_bfloat16* __restrict__ C3, int N, int K3)
{
    constexpr int S = 4;
    constexpr int LDS = 24;
    constexpr int MI = WM / 16, NJ = WN / 16;
    constexpr int WROWS = BM / WM;
    constexpr int NW = TH / 32;
    constexpr int ABYTES = BM * LDS * 2;
    constexpr int BBYTES = BN * LDS * 2;
    __shared__ alignas(16) __nv_bfloat16 Asm[S][BM][LDS];
    __shared__ alignas(16) __nv_bfloat16 Bsm[S][BN][LDS];
    __shared__ float stage[EMIT3 ? NW : 1][16][20];

    const int tid = threadIdx.x;
    const int lane = tid & 31;
    const int m0  = blockIdx.x * BM;
    const int n0  = blockIdx.y * BN;
    const int wid = tid >> 5;
    const int wm  = wid % WROWS;
    const int wn  = wid / WROWS;

    static_assert(BM * 2 <= TH && BN * 2 <= TH, "");
    const int row2 = tid >> 1, col2 = (tid & 1) * 8;
    const bool aok = (BM * 2 == TH) || (tid < BM * 2);
    const bool bok = (BN * 2 == TH) || (tid < BN * 2);

    const u32 a_dst0 = cvta_smem(&Asm[0][0][0]) + row2 * (LDS * 2) + col2 * 2;
    const u32 b_dst0 = cvta_smem(&Bsm[0][0][0]) + row2 * (LDS * 2) + col2 * 2;
    const __nv_bfloat16* a_src = A + (size_t)(m0 + row2) * K3 + col2;
    const __nv_bfloat16* b_src = W + (size_t)(n0 + row2) * K3 + col2;

#define LD_TILE(KT, SS)                                                       \
    {                                                                         \
        if (aok) cpa16(a_dst0 + (SS) * ABYTES, a_src + (size_t)(KT) * 16);    \
        if (bok) cpa16(b_dst0 + (SS) * BBYTES, b_src + (size_t)(KT) * 16);    \
        CPA_COMMIT();                                                         \
    }

    wmma::fragment<wmma::accumulator, 16, 16, 16, float> acc[MI][NJ];
#pragma unroll
    for (int i = 0; i < MI; i++)
#pragma unroll
        for (int j = 0; j < NJ; j++) wmma::fill_fragment(acc[i][j], 0.f);

    const int nK = K3 / 16;
    LD_TILE(0, 0);
    LD_TILE(1, 1);
    LD_TILE(2, 2);

    for (int kt = 0; kt < nK; kt++) {
        CPA_WAIT2();
        __syncthreads();
        if (kt + 3 < nK) {
            LD_TILE(kt + 3, (kt + 3) & 3);
        } else {
            CPA_COMMIT();
        }
        const int s = kt & 3;

        wmma::fragment<wmma::matrix_a, 16, 16, 16, __nv_bfloat16, wmma::row_major> af[MI];
        wmma::fragment<wmma::matrix_b, 16, 16, 16, __nv_bfloat16, wmma::col_major> bf_[NJ];
#pragma unroll
        for (int i = 0; i < MI; i++)
            wmma::load_matrix_sync(af[i], &Asm[s][wm * WM + i * 16][0], LDS);
#pragma unroll
        for (int j = 0; j < NJ; j++)
            wmma::load_matrix_sync(bf_[j], &Bsm[s][wn * WN + j * 16][0], LDS);
#pragma unroll
        for (int i = 0; i < MI; i++)
#pragma unroll
            for (int j = 0; j < NJ; j++)
                wmma::mma_sync(acc[i][j], af[i], bf_[j], acc[i][j]);
    }
#undef LD_TILE

    if (!EMIT3) {
#pragma unroll
        for (int i = 0; i < MI; i++)
#pragma unroll
            for (int j = 0; j < NJ; j++)
                wmma::store_matrix_sync(
                    &C[(size_t)(m0 + wm * WM + i * 16) * N + n0 + wn * WN + j * 16],
                    acc[i][j], N, wmma::mem_row_major);
    } else {
#pragma unroll
        for (int i = 0; i < MI; i++)
#pragma unroll
            for (int j = 0; j < NJ; j++) {
                wmma::store_matrix_sync(&stage[wid][0][0], acc[i][j], 20,
                                        wmma::mem_row_major);
                __syncwarp();
#pragma unroll
                for (int e = 0; e < 4; e++) {
                    const int idx = lane + e * 32;       // pair index 0..127
                    const int r = idx >> 3;              // row 0..15
                    const int c = (idx & 7) * 2;         // col 0,2,..,14
                    const float v0 = stage[wid][r][c];
                    const float v1 = stage[wid][r][c + 1];
                    const int m = m0 + wm * WM + i * 16 + r;
                    const int n = n0 + wn * WN + j * 16 + c;
                    *(float2*)&C[(size_t)m * N + n] = make_float2(v0, v1);
                    const __nv_bfloat16 h0 = __float2bfloat16(v0);
                    const __nv_bfloat16 l0 =
                        __float2bfloat16(v0 - __bfloat162float(h0));
                    const __nv_bfloat16 h1 = __float2bfloat16(v1);
                    const __nv_bfloat16 l1 =
                        __float2bfloat16(v1 - __bfloat162float(h1));
                    __nv_bfloat16* o = C3 + (size_t)m * 3 * N + n;
                    const u32 hp = pack_bf2(h0, h1);
                    *(u32*)&o[0] = hp;
                    *(u32*)&o[N] = hp;
                    *(u32*)&o[2 * N] = pack_bf2(l0, l1);
                }
                __syncwarp();
            }
    }
}

// ---------------------------------------------------------------------------
// fp32 GEMM (FFMA f32x2). Optional out3: also emit [hi|hi|lo] bf16 split.
// ---------------------------------------------------------------------------
template<int BM, int BN, int BK, int TM, int TN, int TH, int KSPLIT>
__global__ void __launch_bounds__(TH) gemm_t(
    const float* __restrict__ A, const float* __restrict__ W,
    const float* __restrict__ bias, float* __restrict__ C,
    __nv_bfloat16* __restrict__ out3,
    int N, int K, int lda, int epi)
{
    static_assert(TM % 4 == 0 && TN % 4 == 0, "");
    constexpr int PAD = 4;
    __shared__ float As[2][BK][BM + PAD];
    __shared__ float Ws[2][BK][BN + PAD];
    constexpr int A4 = BM * BK / (TH * 4);
    constexpr int B4 = BN * BK / (TH * 4);
    constexpr int KQ = BK / 4;
    constexpr int TNH = TN / 2;

    const int tid = threadIdx.x;
    const int m0  = blockIdx.x * BM;
    const int n0  = blockIdx.y * BN;
    const int tx  = tid % (BN / TN);
    const int ty  = tid / (BN / TN);

    const int klen = K / KSPLIT;
    const int kb   = (KSPLIT > 1) ? blockIdx.z * klen : 0;
    float* Cout = (KSPLIT > 1)
        ? C + (size_t)blockIdx.z * gridDim.x * BM * N
        : C;

    ull acc[TM][TNH];
#pragma unroll
    for (int i = 0; i < TM; i++)
#pragma unroll
        for (int j = 0; j < TNH; j++) acc[i][j] = 0ull;

    float4 ar[A4], wr[B4];

#define LOADR(K0)                                                             \
    {                                                                         \
        _Pragma("unroll")                                                     \
        for (int t = 0; t < A4; t++) {                                        \
            int idx = tid + t * TH;                                           \
            int row = idx / KQ, kq = idx % KQ;                                \
            ar[t] = *(const float4*)(A + (size_t)(m0 + row) * lda + (K0) + kq * 4); \
        }                                                                     \
        _Pragma("unroll")                                                     \
        for (int t = 0; t < B4; t++) {                                        \
            int idx = tid + t * TH;                                           \
            int row = idx / KQ, kq = idx % KQ;                                \
            int n = n0 + row;                                                 \
            wr[t] = (n < N) ? *(const float4*)(W + (size_t)n * K + (K0) + kq * 4) \
                            : make_float4(0.f, 0.f, 0.f, 0.f);                \
        }                                                                     \
    }

#define STS(S)                                                                \
    {                                                                         \
        _Pragma("unroll")                                                     \
        for (int t = 0; t < A4; t++) {                                        \
            int idx = tid + t * TH;                                           \
            int row = idx / KQ, kq = idx % KQ;                                \
            As[S][kq * 4 + 0][row] = ar[t].x;                                 \
            As[S][kq * 4 + 1][row] = ar[t].y;                                 \
            As[S][kq * 4 + 2][row] = ar[t].z;                                 \
            As[S][kq * 4 + 3][row] = ar[t].w;                                 \
        }                                                                     \
        _Pragma("unroll")                                                     \
        for (int t = 0; t < B4; t++) {                                        \
            int idx = tid + t * TH;                                           \
            int row = idx / KQ, kq = idx % KQ;                                \
            Ws[S][kq * 4 + 0][row] = wr[t].x;                                 \
            Ws[S][kq * 4 + 1][row] = wr[t].y;                                 \
            Ws[S][kq * 4 + 2][row] = wr[t].z;                                 \
            Ws[S][kq * 4 + 3][row] = wr[t].w;                                 \
        }                                                                     \
    }

    LOADR(kb);
    STS(0);
    __syncthreads();

    int s = 0;
    for (int k0 = kb; k0 < kb + klen; k0 += BK) {
        const bool more = (k0 + BK) < (kb + klen);
        if (more) LOADR(k0 + BK);

#pragma unroll
        for (int k = 0; k < BK; k++) {
            float a[TM];
#pragma unroll
            for (int q = 0; q < TM / 4; q++)
                *(float4*)&a[q * 4] = *(const float4*)&As[s][k][ty * TM + q * 4];

            ull w2[TNH];
#pragma unroll
            for (int q = 0; q < TN / 4; q++) {
                ulonglong2 wv = *(const ulonglong2*)&Ws[s][k][tx * TN + q * 4];
                w2[q * 2 + 0] = wv.x;
                w2[q * 2 + 1] = wv.y;
            }

#pragma unroll
            for (int i = 0; i < TM; i++) {
                const ull a2 = pk2(a[i], a[i]);
#pragma unroll
                for (int j = 0; j < TNH; j++) fma2(acc[i][j], a2, w2[j]);
            }
        }

        if (more) STS(s ^ 1);
        __syncthreads();
        s ^= 1;
    }
#undef LOADR
#undef STS

#pragma unroll
    for (int i = 0; i < TM; i++) {
        float r[TN];
#pragma unroll
        for (int j = 0; j < TNH; j++) {
            float2 v = upk2(acc[i][j]);
            r[2 * j] = v.x; r[2 * j + 1] = v.y;
        }
        const int m = m0 + ty * TM + i;
#pragma unroll
        for (int q = 0; q < TN / 4; q++) {
            const int n = n0 + tx * TN + q * 4;
            if (n >= N) continue;
            float4 v = *(float4*)&r[q * 4];
            if (epi >= 1) {
                float4 bv = *(const float4*)&bias[n];
                v.x += bv.x; v.y += bv.y; v.z += bv.z; v.w += bv.w;
            }
            if (epi == 2) {
                v.x = (v.x > 20.f) ? v.x : log1pf(__expf(v.x));
                v.y = (v.y > 20.f) ? v.y : log1pf(__expf(v.y));
                v.z = (v.z > 20.f) ? v.z : log1pf(__expf(v.z));
                v.w = (v.w > 20.f) ? v.w : log1pf(__expf(v.w));
            }
            *(float4*)&Cout[(size_t)m * N + n] = v;
            if (out3) {
                const float vv[4] = {v.x, v.y, v.z, v.w};
                __nv_bfloat16* o = out3 + (size_t)m * 3 * N + n;
#pragma unroll
                for (int e = 0; e < 4; e += 2) {
                    const __nv_bfloat16 h0 = __float2bfloat16(vv[e]);
                    const __nv_bfloat16 l0 =
                        __float2bfloat16(vv[e] - __bfloat162float(h0));
                    const __nv_bfloat16 h1 = __float2bfloat16(vv[e + 1]);
                    const __nv_bfloat16 l1 =
                        __float2bfloat16(vv[e + 1] - __bfloat162float(h1));
                    const u32 hp = pack_bf2(h0, h1);
                    *(u32*)&o[e] = hp;
                    *(u32*)&o[N + e] = hp;
                    *(u32*)&o[2 * N + e] = pack_bf2(l0, l1);
                }
            }
        }
    }
}

// ---------------------------------------------------------------------------
__global__ void reduce_part_kernel(const float* __restrict__ part,
                                   float* __restrict__ out)
{
    const int total4 = MROWS * XDBL_W / 4;
    int idx = blockIdx.x * blockDim.x + threadIdx.x;
    if (idx >= total4) return;
    const float4* p = (const float4*)part;
    float4 v = p[idx];
#pragma unroll
    for (int s = 1; s < KSPL; s++) {
        float4 w = p[idx + (size_t)s * total4];
        v.x += w.x; v.y += w.y; v.z += w.z; v.w += w.w;
    }
    ((float4*)out)[idx] = v;
}

// ---------------------------------------------------------------------------
// Causal depthwise conv (width 4) + bias + SiLU; 4 channels per thread.
// ---------------------------------------------------------------------------
__global__ void conv_silu_kernel(const float* __restrict__ xz,
                                 const float* __restrict__ cw,
                                 const float* __restrict__ cb,
                                 float* __restrict__ xc)
{
    int idx = blockIdx.x * blockDim.x + threadIdx.x;   // quad index
    if (idx >= MROWS * D_INNER / 4) return;
    const int d  = (idx & 127) * 4;
    const int bl = idx >> 7;
    const int l  = bl & (L_SEQ - 1);

    float4 w0 = *(const float4*)&cw[(d + 0) * 4];
    float4 w1 = *(const float4*)&cw[(d + 1) * 4];
    float4 w2 = *(const float4*)&cw[(d + 2) * 4];
    float4 w3 = *(const float4*)&cw[(d + 3) * 4];
    float4 bv = *(const float4*)&cb[d];

    const float* base = xz + (size_t)bl * (2 * D_INNER) + d;
    const int stride = 2 * D_INNER;

    float4 acc = bv;
    {
        float4 x = *(const float4*)base;
        acc.x = fmaf(x.x, w0.w, acc.x); acc.y = fmaf(x.y, w1.w, acc.y);
        acc.z = fmaf(x.z, w2.w, acc.z); acc.w = fmaf(x.w, w3.w, acc.w);
    }
    if (l >= 1) {
        float4 x = *(const float4*)(base - stride);
        acc.x = fmaf(x.x, w0.z, acc.x); acc.y = fmaf(x.y, w1.z, acc.y);
        acc.z = fmaf(x.z, w2.z, acc.z); acc.w = fmaf(x.w, w3.z, acc.w);
    }
    if (l >= 2) {
        float4 x = *(const float4*)(base - 2 * stride);
        acc.x = fmaf(x.x, w0.y, acc.x); acc.y = fmaf(x.y, w1.y, acc.y);
        acc.z = fmaf(x.z, w2.y, acc.z); acc.w = fmaf(x.w, w3.y, acc.w);
    }
    if (l >= 3) {
        float4 x = *(const float4*)(base - 3 * stride);
        acc.x = fmaf(x.x, w0.x, acc.x); acc.y = fmaf(x.y, w1.x, acc.y);
        acc.z = fmaf(x.z, w2.x, acc.z); acc.w = fmaf(x.w, w3.x, acc.w);
    }

    acc.x = acc.x / (1.f + __expf(-acc.x));
    acc.y = acc.y / (1.f + __expf(-acc.y));
    acc.z = acc.z / (1.f + __expf(-acc.z));
    acc.w = acc.w / (1.f + __expf(-acc.w));
    *(float4*)&xc[(size_t)bl * D_INNER + d] = acc;
}

// ---------------------------------------------------------------------------
// Selective scan, depth-4 prefetch with NAMED registers (no spills).
// ---------------------------------------------------------------------------
__global__ void __launch_bounds__(256) scan_kernel(
    const float* __restrict__ dtbuf,
    const float* __restrict__ xc,
    const float* __restrict__ xdbl,
    const float* __restrict__ A_log,
    const float* __restrict__ Dskip,
    float* __restrict__ y)
{
    const int warp = (blockIdx.x * blockDim.x + threadIdx.x) >> 5;
    const int lane = threadIdx.x & 31;
    const int grp  = lane >> 4;
    const int n    = lane & 15;
    const int ch   = warp * 2 + grp;
    const int b    = ch >> 9;
    const int d    = ch & 511;

    const float A  = -__expf(A_log[d * 16 + n]);
    const float Dv = Dskip[d];

    float h = 0.f;
    const size_t bl = (size_t)b * L_SEQ;
    const float* pdt = dtbuf + bl * D_INNER + d;
    const float* pu  = xc    + bl * D_INNER + d;
    const float* pB  = xdbl  + bl * XDBL_W + DT_RANK + n;
    float*       pyo = y     + bl * D_INNER + d;

    float dt0 = pdt[0 * D_INNER], u0 = pu[0 * D_INNER];
    float B0 = pB[0 * XDBL_W], C0 = pB[0 * XDBL_W + D_STATE];
    float dt1 = pdt[1 * D_INNER], u1 = pu[1 * D_INNER];
    float B1 = pB[1 * XDBL_W], C1 = pB[1 * XDBL_W + D_STATE];
    float dt2 = pdt[2 * D_INNER], u2 = pu[2 * D_INNER];
    float B2 = pB[2 * XDBL_W], C2 = pB[2 * XDBL_W + D_STATE];
    float dt3 = pdt[3 * D_INNER], u3 = pu[3 * D_INNER];
    float B3 = pB[3 * XDBL_W], C3v = pB[3 * XDBL_W + D_STATE];

#define SCAN_STEP(DT, U, BV, CV, LOFF)                                        \
    {                                                                         \
        const float dA = __expf((DT) * A);                                    \
        h = fmaf(dA, h, (DT) * (BV) * (U));                                   \
        float p = h * (CV);                                                   \
        p += __shfl_xor_sync(0xffffffffu, p, 1);                              \
        p += __shfl_xor_sync(0xffffffffu, p, 2);                              \
        p += __shfl_xor_sync(0xffffffffu, p, 4);                              \
        p += __shfl_xor_sync(0xffffffffu, p, 8);                              \
        if (n == 0)                                                           \
            pyo[(size_t)(l + (LOFF)) * D_INNER] = p + (U) * Dv;               \
        const int ln = (l + (LOFF) + 4 < L_SEQ) ? (l + (LOFF) + 4)            \
                                                : (L_SEQ - 1);                \
        DT = pdt[(size_t)ln * D_INNER];                                       \
        U  = pu [(size_t)ln * D_INNER];                                       \
        BV = pB [(size_t)ln * XDBL_W];                                        \
        CV = pB [(size_t)ln * XDBL_W + D_STATE];                              \
    }

    for (int l = 0; l < L_SEQ; l += 4) {
        SCAN_STEP(dt0, u0, B0, C0, 0);
        SCAN_STEP(dt1, u1, B1, C1, 1);
        SCAN_STEP(dt2, u2, B2, C2, 2);
        SCAN_STEP(dt3, u3, B3, C3v, 3);
    }
#undef SCAN_STEP
}

// ---------------------------------------------------------------------------
__global__ void head1_kernel(const float* __restrict__ h,
                             const float* __restrict__ p1w,
                             const float* __restrict__ p1b,
                             float* __restrict__ fc)
{
    int idx = blockIdx.x * blockDim.x + threadIdx.x;
    if (idx >= B_SZ * D_FF) return;
    const int b = idx / D_FF;
    const int f = idx - b * D_FF;
    const float4* hp = (const float4*)(h + ((size_t)b * L_SEQ + (L_SEQ - 1)) * D_MODEL);
    const float4* wp = (const float4*)(p1w + (size_t)f * D_MODEL);
    float acc = 0.f;
#pragma unroll 8
    for (int k = 0; k < D_MODEL / 4; k++) {
        float4 a = hp[k], w = wp[k];
        acc += a.x * w.x + a.y * w.y + a.z * w.z + a.w * w.w;
    }
    acc += p1b[f];
    fc[idx] = 0.5f * acc * (1.f + erff(acc * 0.70710678118f));
}

__global__ void head2_kernel(const float* __restrict__ fc,
                             const float* __restrict__ p2w,
                             const float* __restrict__ p2b,
                             float* __restrict__ out)
{
    const int b = blockIdx.x;
    const int t = threadIdx.x;
    float acc = 0.f;
    for (int k = t; k < D_FF; k += 256) acc += fc[b * D_FF + k] * p2w[k];
    __shared__ float s[8];
#pragma unroll
    for (int o = 16; o; o >>= 1) acc += __shfl_xor_sync(0xffffffffu, acc, o);
    if ((t & 31) == 0) s[t >> 5] = acc;
    __syncthreads();
    if (t < 8) {
        float v = s[t];
#pragma unroll
        for (int o = 4; o; o >>= 1) v += __shfl_xor_sync(0x000000ffu, v, o);
        if (t == 0) out[b] = v + p2b[0];
    }
}

// ---------------------------------------------------------------------------
extern "C" void kernel_launch(void* const* d_in, const int* in_sizes, int n_in,
                              void* d_out, int out_size)
{
    (void)in_sizes; (void)n_in; (void)out_size;
    const float* x          = (const float*)d_in[0];
    const float* in_w       = (const float*)d_in[1];
    const float* in_b       = (const float*)d_in[2];
    const float* in_proj_w  = (const float*)d_in[3];
    const float* conv_w     = (const float*)d_in[4];
    const float* conv_b     = (const float*)d_in[5];
    const float* x_proj_w   = (const float*)d_in[6];
    const float* dt_w       = (const float*)d_in[7];
    const float* dt_b       = (const float*)d_in[8];
    const float* A_log      = (const float*)d_in[9];
    const float* D_skip     = (const float*)d_in[10];
    const float* out_proj_w = (const float*)d_in[11];
    const float* p1_w       = (const float*)d_in[12];
    const float* p1_b       = (const float*)d_in[13];
    const float* p2_w       = (const float*)d_in[14];
    const float* p2_b       = (const float*)d_in[15];
    float* out = (float*)d_out;

    float *ph, *pxz, *pxc, *pxdbl, *ppart, *pdt, *py, *pfc;
    __nv_bfloat16 *ph3, *py3, *pw3a, *pw3b;
    cudaGetSymbolAddress((void**)&ph,    g_h);
    cudaGetSymbolAddress((void**)&pxz,   g_xz);
    cudaGetSymbolAddress((void**)&pxc,   g_xc);
    cudaGetSymbolAddress((void**)&pxdbl, g_xdbl);
    cudaGetSymbolAddress((void**)&ppart, g_part);
    cudaGetSymbolAddress((void**)&pdt,   g_dt);
    cudaGetSymbolAddress((void**)&py,    g_y);
    cudaGetSymbolAddress((void**)&pfc,   g_fc);
    cudaGetSymbolAddress((void**)&ph3,   g_h3);
    cudaGetSymbolAddress((void**)&py3,   g_y3);
    cudaGetSymbolAddress((void**)&pw3a,  g_w3a);
    cudaGetSymbolAddress((void**)&pw3b,  g_w3b);

    const size_t off_a = (size_t)2 * D_INNER * 3 * D_MODEL;
    const size_t off_b = (size_t)D_MODEL * 3 * D_INNER;

    // All weight splits once (both layers each)
    split3_kernel<<<(N_LAYERS * 2 * D_INNER * D_MODEL + 255) / 256, 256>>>(
        in_proj_w, pw3a, N_LAYERS * 2 * D_INNER * D_MODEL, D_MODEL, 1);
    split3_kernel<<<(N_LAYERS * D_MODEL * D_INNER + 255) / 256, 256>>>(
        out_proj_w, pw3b, N_LAYERS * D_MODEL * D_INNER, D_INNER, 1);

    // h = x @ in_w^T + in_b  [8192,256], K=32 (FFMA); also emits h3 (split3)
    gemm_t<32, 64, 16, 4, 4, 128, 1><<<dim3(MROWS / 32, D_MODEL / 64), 128>>>(
        x, in_w, in_b, ph, ph3, D_MODEL, ENC_IN, ENC_IN, 1);

    for (int i = 0; i < N_LAYERS; i++) {
        const float* xpw = x_proj_w + (size_t)i * XDBL_W * D_INNER;
        const float* dtw = dt_w     + (size_t)i * D_INNER * DT_RANK;

        // ---- in_proj (wmma, R12 config): xz = h @ ipw^T  [8192,1024] -----
        wmma_gemm<128, 128, 64, 32, 256, 0>
            <<<dim3(MROWS / 128, (2 * D_INNER) / 128), 256>>>(
            ph3, pw3a + i * off_a, pxz, nullptr, 2 * D_INNER, 3 * D_MODEL);

        conv_silu_kernel<<<(MROWS * D_INNER / 4) / 256, 256>>>(pxz,
                conv_w + (size_t)i * D_INNER * D_CONV,
                conv_b + (size_t)i * D_INNER, pxc);

        // xdbl partials: [8192,48], K=512 split 4 (FFMA)
        gemm_t<32, 64, 16, 4, 4, 128, KSPL><<<dim3(MROWS / 32, 1, KSPL), 128>>>(
            pxc, xpw, nullptr, ppart, nullptr, XDBL_W, D_INNER, D_INNER, 0);
        reduce_part_kernel<<<(MROWS * XDBL_W / 4 + 255) / 256, 256>>>(ppart, pxdbl);

        // dt = softplus(xdbl[:, :16] @ dtw^T + dt_b) [8192,512], K=16 (FFMA)
        gemm_t<32, 64, 16, 4, 4, 128, 1><<<dim3(MROWS / 32, D_INNER / 64), 128>>>(
            pxdbl, dtw, dt_b + (size_t)i * D_INNER, pdt, nullptr,
            D_INNER, DT_RANK, XDBL_W, 2);

        // y_raw = selective scan
        scan_kernel<<<(B_SZ * D_INNER / 2) * 32 / 256, 256>>>(pdt, pxc, pxdbl,
                A_log  + (size_t)i * D_INNER * D_STATE,
                D_skip + (size_t)i * D_INNER, py);

        // ---- out_proj (wmma, 512 CTAs): h = (y*silu(z)) @ opw^T ----------
        gate_split3_kernel<<<(MROWS * D_INNER / 2 + 255) / 256, 256>>>(py, pxz, py3);
        wmma_gemm<32, 128, 32, 16, 256, 1>
            <<<dim3(MROWS / 32, D_MODEL / 128), 256>>>(
            py3, pw3b + i * off_b, ph, ph3, D_MODEL, 3 * D_INNER);
    }

    head1_kernel<<<(B_SZ * D_FF) / 256, 256>>>(ph, p1_w, p1_b, pfc);
    head2_kernel<<<B_SZ, 256>>>(pfc, p2_w, p2_b, out);
}

// round 16
// speedup vs baseline: 1.1639x; 1.1639x over previous
#include <cuda_runtime.h>
#include <cuda_bf16.h>
#include <mma.h>
#include <math.h>
#include <stdint.h>

using namespace nvcuda;

#define B_SZ    8
#define L_SEQ   1024
#define ENC_IN  32
#define D_MODEL 256
#define D_INNER 512
#define D_STATE 16
#define D_CONV  4
#define DT_RANK 16
#define N_LAYERS 2
#define D_FF    1024
#define MROWS   (B_SZ * L_SEQ)   // 8192
#define XDBL_W  (DT_RANK + 2 * D_STATE)   // 48
#define KSPL    4

typedef unsigned long long ull;
typedef unsigned int u32;

// ---------------- scratch (static device globals; no allocs allowed) -------
__device__ float g_h   [MROWS * D_MODEL];
__device__ float g_xz  [MROWS * 2 * D_INNER];
__device__ float g_xc  [MROWS * D_INNER];
__device__ float g_xdbl[MROWS * XDBL_W];
__device__ float g_part[KSPL * MROWS * XDBL_W];
__device__ float g_dt  [MROWS * D_INNER];
__device__ float g_y   [MROWS * D_INNER];
__device__ float g_fc  [B_SZ * D_FF];

__device__ __nv_bfloat16 g_h3 [MROWS * 3 * D_MODEL];
__device__ __nv_bfloat16 g_y3 [MROWS * 3 * D_INNER];
__device__ __nv_bfloat16 g_w3a[N_LAYERS * 2 * D_INNER * 3 * D_MODEL];
__device__ __nv_bfloat16 g_w3b[N_LAYERS * D_MODEL * 3 * D_INNER];

// ---------------- packed f32x2 helpers -------------------------------------
__device__ __forceinline__ ull pk2(float x, float y) {
    ull r;
    asm("mov.b64 %0, {%1, %2};" : "=l"(r) : "f"(x), "f"(y));
    return r;
}
__device__ __forceinline__ void fma2(ull& c, ull a, ull b) {
    asm("fma.rn.f32x2 %0, %1, %2, %0;" : "+l"(c) : "l"(a), "l"(b));
}
__device__ __forceinline__ float2 upk2(ull v) {
    float2 r;
    asm("mov.b64 {%0, %1}, %2;" : "=f"(r.x), "=f"(r.y) : "l"(v));
    return r;
}
__device__ __forceinline__ u32 pack_bf2(__nv_bfloat16 a, __nv_bfloat16 b) {
    __nv_bfloat162 t = __halves2bfloat162(a, b);
    return *(u32*)&t;
}
__device__ __forceinline__ u32 cvta_smem(const void* p) {
    u32 a;
    asm("{ .reg .u64 t; cvta.to.shared.u64 t, %1; cvt.u32.u64 %0, t; }"
        : "=r"(a) : "l"(p));
    return a;
}
__device__ __forceinline__ void cpa16(u32 s, const void* g) {
    asm volatile("cp.async.cg.shared.global [%0], [%1], 16;"
                 :: "r"(s), "l"(g));
}
#define CPA_COMMIT() asm volatile("cp.async.commit_group;" ::: "memory")
#define CPA_WAIT2()  asm volatile("cp.async.wait_group 2;" ::: "memory")

// ---------------------------------------------------------------------------
// hi/lo split for weights: mode 1 row layout [hi | lo | hi].
// ---------------------------------------------------------------------------
__global__ void split3_kernel(const float* __restrict__ in,
                              __nv_bfloat16* __restrict__ out,
                              int total, int K, int mode)
{
    int idx = blockIdx.x * blockDim.x + threadIdx.x;
    if (idx >= total) return;
    const float x = in[idx];
    const __nv_bfloat16 hi = __float2bfloat16(x);
    const __nv_bfloat16 lo = __float2bfloat16(x - __bfloat162float(hi));
    const int r = idx / K;
    const int k = idx - r * K;
    __nv_bfloat16* o = out + (size_t)r * 3 * K + k;
    o[0] = hi;
    o[K] = mode ? lo : hi;
    o[2 * K] = mode ? hi : lo;
}

// ---------------------------------------------------------------------------
// Fused z-gate + hi/lo split (A-mode [hi|hi|lo]) for y -> y3; 2 d per thread.
// ---------------------------------------------------------------------------
__global__ void gate_split3_kernel(const float* __restrict__ y,
                                   const float* __restrict__ xz,
                                   __nv_bfloat16* __restrict__ out)
{
    int idx = blockIdx.x * blockDim.x + threadIdx.x;       // pair index
    if (idx >= MROWS * D_INNER / 2) return;
    const int r = idx >> 8;                                // 256 pairs/row
    const int d = (idx & 255) * 2;
    const float2 zv = *(const float2*)&xz[(size_t)r * (2 * D_INNER) + D_INNER + d];
    const float2 yv = *(const float2*)&y[(size_t)r * D_INNER + d];
    const float x0 = yv.x * (zv.x / (1.f + __expf(-zv.x)));
    const float x1 = yv.y * (zv.y / (1.f + __expf(-zv.y)));
    const __nv_bfloat16 h0 = __float2bfloat16(x0);
    const __nv_bfloat16 l0 = __float2bfloat16(x0 - __bfloat162float(h0));
    const __nv_bfloat16 h1 = __float2bfloat16(x1);
    const __nv_bfloat16 l1 = __float2bfloat16(x1 - __bfloat162float(h1));
    __nv_bfloat16* o = out + (size_t)r * 3 * D_INNER + d;
    const u32 hp = pack_bf2(h0, h1);
    *(u32*)&o[0] = hp;
    *(u32*)&o[D_INNER] = hp;
    *(u32*)&o[2 * D_INNER] = pack_bf2(l0, l1);
}

// ---------------------------------------------------------------------------
// wmma bf16 GEMM with 4-stage cp.async pipeline (KD=16 per stage).
//   C[M,N] = A3[M,K3] @ W3[N,K3]^T
// EMIT3: also write C3[M,3N] = [hi|hi|lo] split of C.
// ---------------------------------------------------------------------------
template<int BM, int BN, int WM, int WN, int TH, int EMIT3>
__global__ void __launch_bounds__(TH) wmma_gemm(
    const __nv_bfloat16* __restrict__ A, const __nv_bfloat16* __restrict__ W,
    float* __restrict__ C, __nv_bfloat16* __restrict__ C3, int N, int K3)
{
    constexpr int S = 4;
    constexpr int LDS = 24;
    constexpr int MI = WM / 16, NJ = WN / 16;
    constexpr int WROWS = BM / WM;
    constexpr int NW = TH / 32;
    constexpr int ABYTES = BM * LDS * 2;
    constexpr int BBYTES = BN * LDS * 2;
    __shared__ alignas(16) __nv_bfloat16 Asm[S][BM][LDS];
    __shared__ alignas(16) __nv_bfloat16 Bsm[S][BN][LDS];
    __shared__ float stage[EMIT3 ? NW : 1][16][20];

    const int tid = threadIdx.x;
    const int lane = tid & 31;
    const int m0  = blockIdx.x * BM;
    const int n0  = blockIdx.y * BN;
    const int wid = tid >> 5;
    const int wm  = wid % WROWS;
    const int wn  = wid / WROWS;

    static_assert(BM * 2 <= TH && BN * 2 <= TH, "");
    const int row2 = tid >> 1, col2 = (tid & 1) * 8;
    const bool aok = (BM * 2 == TH) || (tid < BM * 2);
    const bool bok = (BN * 2 == TH) || (tid < BN * 2);

    const u32 a_dst0 = cvta_smem(&Asm[0][0][0]) + row2 * (LDS * 2) + col2 * 2;
    const u32 b_dst0 = cvta_smem(&Bsm[0][0][0]) + row2 * (LDS * 2) + col2 * 2;
    const __nv_bfloat16* a_src = A + (size_t)(m0 + row2) * K3 + col2;
    const __nv_bfloat16* b_src = W + (size_t)(n0 + row2) * K3 + col2;

#define LD_TILE(KT, SS)                                                       \
    {                                                                         \
        if (aok) cpa16(a_dst0 + (SS) * ABYTES, a_src + (size_t)(KT) * 16);    \
        if (bok) cpa16(b_dst0 + (SS) * BBYTES, b_src + (size_t)(KT) * 16);    \
        CPA_COMMIT();                                                         \
    }

    wmma::fragment<wmma::accumulator, 16, 16, 16, float> acc[MI][NJ];
#pragma unroll
    for (int i = 0; i < MI; i++)
#pragma unroll
        for (int j = 0; j < NJ; j++) wmma::fill_fragment(acc[i][j], 0.f);

    const int nK = K3 / 16;
    LD_TILE(0, 0);
    LD_TILE(1, 1);
    LD_TILE(2, 2);

    for (int kt = 0; kt < nK; kt++) {
        CPA_WAIT2();
        __syncthreads();
        if (kt + 3 < nK) {
            LD_TILE(kt + 3, (kt + 3) & 3);
        } else {
            CPA_COMMIT();
        }
        const int s = kt & 3;

        wmma::fragment<wmma::matrix_a, 16, 16, 16, __nv_bfloat16, wmma::row_major> af[MI];
        wmma::fragment<wmma::matrix_b, 16, 16, 16, __nv_bfloat16, wmma::col_major> bf_[NJ];
#pragma unroll
        for (int i = 0; i < MI; i++)
            wmma::load_matrix_sync(af[i], &Asm[s][wm * WM + i * 16][0], LDS);
#pragma unroll
        for (int j = 0; j < NJ; j++)
            wmma::load_matrix_sync(bf_[j], &Bsm[s][wn * WN + j * 16][0], LDS);
#pragma unroll
        for (int i = 0; i < MI; i++)
#pragma unroll
            for (int j = 0; j < NJ; j++)
                wmma::mma_sync(acc[i][j], af[i], bf_[j], acc[i][j]);
    }
#undef LD_TILE

    if (!EMIT3) {
#pragma unroll
        for (int i = 0; i < MI; i++)
#pragma unroll
            for (int j = 0; j < NJ; j++)
                wmma::store_matrix_sync(
                    &C[(size_t)(m0 + wm * WM + i * 16) * N + n0 + wn * WN + j * 16],
                    acc[i][j], N, wmma::mem_row_major);
    } else {
#pragma unroll
        for (int i = 0; i < MI; i++)
#pragma unroll
            for (int j = 0; j < NJ; j++) {
                wmma::store_matrix_sync(&stage[wid][0][0], acc[i][j], 20,
                                        wmma::mem_row_major);
                __syncwarp();
#pragma unroll
                for (int e = 0; e < 4; e++) {
                    const int idx = lane + e * 32;       // pair index 0..127
                    const int r = idx >> 3;              // row 0..15
                    const int c = (idx & 7) * 2;         // col 0,2,..,14
                    const float v0 = stage[wid][r][c];
                    const float v1 = stage[wid][r][c + 1];
                    const int m = m0 + wm * WM + i * 16 + r;
                    const int n = n0 + wn * WN + j * 16 + c;
                    *(float2*)&C[(size_t)m * N + n] = make_float2(v0, v1);
                    const __nv_bfloat16 h0 = __float2bfloat16(v0);
                    const __nv_bfloat16 l0 =
                        __float2bfloat16(v0 - __bfloat162float(h0));
                    const __nv_bfloat16 h1 = __float2bfloat16(v1);
                    const __nv_bfloat16 l1 =
                        __float2bfloat16(v1 - __bfloat162float(h1));
                    __nv_bfloat16* o = C3 + (size_t)m * 3 * N + n;
                    const u32 hp = pack_bf2(h0, h1);
                    *(u32*)&o[0] = hp;
                    *(u32*)&o[N] = hp;
                    *(u32*)&o[2 * N] = pack_bf2(l0, l1);
                }
                __syncwarp();
            }
    }
}

// ---------------------------------------------------------------------------
// fp32 GEMM (FFMA f32x2). Optional out3: also emit [hi|hi|lo] bf16 split.
// ---------------------------------------------------------------------------
template<int BM, int BN, int BK, int TM, int TN, int TH, int KSPLIT>
__global__ void __launch_bounds__(TH) gemm_t(
    const float* __restrict__ A, const float* __restrict__ W,
    const float* __restrict__ bias, float* __restrict__ C,
    __nv_bfloat16* __restrict__ out3,
    int N, int K, int lda, int epi)
{
    static_assert(TM % 4 == 0 && TN % 4 == 0, "");
    constexpr int PAD = 4;
    __shared__ float As[2][BK][BM + PAD];
    __shared__ float Ws[2][BK][BN + PAD];
    constexpr int A4 = BM * BK / (TH * 4);
    constexpr int B4 = BN * BK / (TH * 4);
    constexpr int KQ = BK / 4;
    constexpr int TNH = TN / 2;

    const int tid = threadIdx.x;
    const int m0  = blockIdx.x * BM;
    const int n0  = blockIdx.y * BN;
    const int tx  = tid % (BN / TN);
    const int ty  = tid / (BN / TN);

    const int klen = K / KSPLIT;
    const int kb   = (KSPLIT > 1) ? blockIdx.z * klen : 0;
    float* Cout = (KSPLIT > 1)
        ? C + (size_t)blockIdx.z * gridDim.x * BM * N
        : C;

    ull acc[TM][TNH];
#pragma unroll
    for (int i = 0; i < TM; i++)
#pragma unroll
        for (int j = 0; j < TNH; j++) acc[i][j] = 0ull;

    float4 ar[A4], wr[B4];

#define LOADR(K0)                                                             \
    {                                                                         \
        _Pragma("unroll")                                                     \
        for (int t = 0; t < A4; t++) {                                        \
            int idx = tid + t * TH;                                           \
            int row = idx / KQ, kq = idx % KQ;                                \
            ar[t] = *(const float4*)(A + (size_t)(m0 + row) * lda + (K0) + kq * 4); \
        }                                                                     \
        _Pragma("unroll")                                                     \
        for (int t = 0; t < B4; t++) {                                        \
            int idx = tid + t * TH;                                           \
            int row = idx / KQ, kq = idx % KQ;                                \
            int n = n0 + row;                                                 \
            wr[t] = (n < N) ? *(const float4*)(W + (size_t)n * K + (K0) + kq * 4) \
                            : make_float4(0.f, 0.f, 0.f, 0.f);                \
        }                                                                     \
    }

#define STS(S)                                                                \
    {                                                                         \
        _Pragma("unroll")                                                     \
        for (int t = 0; t < A4; t++) {                                        \
            int idx = tid + t * TH;                                           \
            int row = idx / KQ, kq = idx % KQ;                                \
            As[S][kq * 4 + 0][row] = ar[t].x;                                 \
            As[S][kq * 4 + 1][row] = ar[t].y;                                 \
            As[S][kq * 4 + 2][row] = ar[t].z;                                 \
            As[S][kq * 4 + 3][row] = ar[t].w;                                 \
        }                                                                     \
        _Pragma("unroll")                                                     \
        for (int t = 0; t < B4; t++) {                                        \
            int idx = tid + t * TH;                                           \
            int row = idx / KQ, kq = idx % KQ;                                \
            Ws[S][kq * 4 + 0][row] = wr[t].x;                                 \
            Ws[S][kq * 4 + 1][row] = wr[t].y;                                 \
            Ws[S][kq * 4 + 2][row] = wr[t].z;                                 \
            Ws[S][kq * 4 + 3][row] = wr[t].w;                                 \
        }                                                                     \
    }

    LOADR(kb);
    STS(0);
    __syncthreads();

    int s = 0;
    for (int k0 = kb; k0 < kb + klen; k0 += BK) {
        const bool more = (k0 + BK) < (kb + klen);
        if (more) LOADR(k0 + BK);

#pragma unroll
        for (int k = 0; k < BK; k++) {
            float a[TM];
#pragma unroll
            for (int q = 0; q < TM / 4; q++)
                *(float4*)&a[q * 4] = *(const float4*)&As[s][k][ty * TM + q * 4];

            ull w2[TNH];
#pragma unroll
            for (int q = 0; q < TN / 4; q++) {
                ulonglong2 wv = *(const ulonglong2*)&Ws[s][k][tx * TN + q * 4];
                w2[q * 2 + 0] = wv.x;
                w2[q * 2 + 1] = wv.y;
            }

#pragma unroll
            for (int i = 0; i < TM; i++) {
                const ull a2 = pk2(a[i], a[i]);
#pragma unroll
                for (int j = 0; j < TNH; j++) fma2(acc[i][j], a2, w2[j]);
            }
        }

        if (more) STS(s ^ 1);
        __syncthreads();
        s ^= 1;
    }
#undef LOADR
#undef STS

#pragma unroll
    for (int i = 0; i < TM; i++) {
        float r[TN];
#pragma unroll
        for (int j = 0; j < TNH; j++) {
            float2 v = upk2(acc[i][j]);
            r[2 * j] = v.x; r[2 * j + 1] = v.y;
        }
        const int m = m0 + ty * TM + i;
#pragma unroll
        for (int q = 0; q < TN / 4; q++) {
            const int n = n0 + tx * TN + q * 4;
            if (n >= N) continue;
            float4 v = *(float4*)&r[q * 4];
            if (epi >= 1) {
                float4 bv = *(const float4*)&bias[n];
                v.x += bv.x; v.y += bv.y; v.z += bv.z; v.w += bv.w;
            }
            if (epi == 2) {
                v.x = (v.x > 20.f) ? v.x : log1pf(__expf(v.x));
                v.y = (v.y > 20.f) ? v.y : log1pf(__expf(v.y));
                v.z = (v.z > 20.f) ? v.z : log1pf(__expf(v.z));
                v.w = (v.w > 20.f) ? v.w : log1pf(__expf(v.w));
            }
            *(float4*)&Cout[(size_t)m * N + n] = v;
            if (out3) {
                const float vv[4] = {v.x, v.y, v.z, v.w};
                __nv_bfloat16* o = out3 + (size_t)m * 3 * N + n;
#pragma unroll
                for (int e = 0; e < 4; e += 2) {
                    const __nv_bfloat16 h0 = __float2bfloat16(vv[e]);
                    const __nv_bfloat16 l0 =
                        __float2bfloat16(vv[e] - __bfloat162float(h0));
                    const __nv_bfloat16 h1 = __float2bfloat16(vv[e + 1]);
                    const __nv_bfloat16 l1 =
                        __float2bfloat16(vv[e + 1] - __bfloat162float(h1));
                    const u32 hp = pack_bf2(h0, h1);
                    *(u32*)&o[e] = hp;
                    *(u32*)&o[N + e] = hp;
                    *(u32*)&o[2 * N + e] = pack_bf2(l0, l1);
                }
            }
        }
    }
}

// ---------------------------------------------------------------------------
__global__ void reduce_part_kernel(const float* __restrict__ part,
                                   float* __restrict__ out)
{
    const int total4 = MROWS * XDBL_W / 4;
    int idx = blockIdx.x * blockDim.x + threadIdx.x;
    if (idx >= total4) return;
    const float4* p = (const float4*)part;
    float4 v = p[idx];
#pragma unroll
    for (int s = 1; s < KSPL; s++) {
        float4 w = p[idx + (size_t)s * total4];
        v.x += w.x; v.y += w.y; v.z += w.z; v.w += w.w;
    }
    ((float4*)out)[idx] = v;
}

// ---------------------------------------------------------------------------
// Causal depthwise conv (width 4) + bias + SiLU; 4 channels per thread.
// ---------------------------------------------------------------------------
__global__ void conv_silu_kernel(const float* __restrict__ xz,
                                 const float* __restrict__ cw,
                                 const float* __restrict__ cb,
                                 float* __restrict__ xc)
{
    int idx = blockIdx.x * blockDim.x + threadIdx.x;   // quad index
    if (idx >= MROWS * D_INNER / 4) return;
    const int d  = (idx & 127) * 4;
    const int bl = idx >> 7;
    const int l  = bl & (L_SEQ - 1);

    float4 w0 = *(const float4*)&cw[(d + 0) * 4];
    float4 w1 = *(const float4*)&cw[(d + 1) * 4];
    float4 w2 = *(const float4*)&cw[(d + 2) * 4];
    float4 w3 = *(const float4*)&cw[(d + 3) * 4];
    float4 bv = *(const float4*)&cb[d];

    const float* base = xz + (size_t)bl * (2 * D_INNER) + d;
    const int stride = 2 * D_INNER;

    float4 acc = bv;
    {
        float4 x = *(const float4*)base;
        acc.x = fmaf(x.x, w0.w, acc.x); acc.y = fmaf(x.y, w1.w, acc.y);
        acc.z = fmaf(x.z, w2.w, acc.z); acc.w = fmaf(x.w, w3.w, acc.w);
    }
    if (l >= 1) {
        float4 x = *(const float4*)(base - stride);
        acc.x = fmaf(x.x, w0.z, acc.x); acc.y = fmaf(x.y, w1.z, acc.y);
        acc.z = fmaf(x.z, w2.z, acc.z); acc.w = fmaf(x.w, w3.z, acc.w);
    }
    if (l >= 2) {
        float4 x = *(const float4*)(base - 2 * stride);
        acc.x = fmaf(x.x, w0.y, acc.x); acc.y = fmaf(x.y, w1.y, acc.y);
        acc.z = fmaf(x.z, w2.y, acc.z); acc.w = fmaf(x.w, w3.y, acc.w);
    }
    if (l >= 3) {
        float4 x = *(const float4*)(base - 3 * stride);
        acc.x = fmaf(x.x, w0.x, acc.x); acc.y = fmaf(x.y, w1.x, acc.y);
        acc.z = fmaf(x.z, w2.x, acc.z); acc.w = fmaf(x.w, w3.x, acc.w);
    }

    acc.x = acc.x / (1.f + __expf(-acc.x));
    acc.y = acc.y / (1.f + __expf(-acc.y));
    acc.z = acc.z / (1.f + __expf(-acc.z));
    acc.w = acc.w / (1.f + __expf(-acc.w));
    *(float4*)&xc[(size_t)bl * D_INNER + d] = acc;
}

// ---------------------------------------------------------------------------
// Selective scan: 4-step batched groups. Independent exp/products up front,
// 4-FMA h-chain, then 4 INTERLEAVED (independent) shuffle-reduction chains.
// Two constant-indexed register buffers give prefetch distance 8.
// ---------------------------------------------------------------------------
__global__ void __launch_bounds__(256) scan_kernel(
    const float* __restrict__ dtbuf,
    const float* __restrict__ xc,
    const float* __restrict__ xdbl,
    const float* __restrict__ A_log,
    const float* __restrict__ Dskip,
    float* __restrict__ y)
{
    const int warp = (blockIdx.x * blockDim.x + threadIdx.x) >> 5;
    const int lane = threadIdx.x & 31;
    const int grp  = lane >> 4;
    const int n    = lane & 15;
    const int ch   = warp * 2 + grp;
    const int b    = ch >> 9;
    const int d    = ch & 511;

    const float A  = -__expf(A_log[d * 16 + n]);
    const float Dv = Dskip[d];

    float h = 0.f;
    const size_t bl = (size_t)b * L_SEQ;
    const float* pdt = dtbuf + bl * D_INNER + d;
    const float* pu  = xc    + bl * D_INNER + d;
    const float* pB  = xdbl  + bl * XDBL_W + DT_RANK + n;
    float*       pyo = y     + bl * D_INNER + d;

    // buffers: [q*4+0]=dt, [q*4+1]=u, [q*4+2]=B, [q*4+3]=C (constant indices)
    float bA[16], bB[16];
#pragma unroll
    for (int q = 0; q < 4; q++) {
        bA[q * 4 + 0] = pdt[(size_t)q * D_INNER];
        bA[q * 4 + 1] = pu [(size_t)q * D_INNER];
        bA[q * 4 + 2] = pB [(size_t)q * XDBL_W];
        bA[q * 4 + 3] = pB [(size_t)q * XDBL_W + D_STATE];
    }
#pragma unroll
    for (int q = 0; q < 4; q++) {
        bB[q * 4 + 0] = pdt[(size_t)(q + 4) * D_INNER];
        bB[q * 4 + 1] = pu [(size_t)(q + 4) * D_INNER];
        bB[q * 4 + 2] = pB [(size_t)(q + 4) * XDBL_W];
        bB[q * 4 + 3] = pB [(size_t)(q + 4) * XDBL_W + D_STATE];
    }

#define SCAN_HALF(BUF, LB, PF)                                                \
    {                                                                         \
        const float e0 = __expf(BUF[0]  * A);                                 \
        const float e1 = __expf(BUF[4]  * A);                                 \
        const float e2 = __expf(BUF[8]  * A);                                 \
        const float e3 = __expf(BUF[12] * A);                                 \
        const float du0 = BUF[0]  * BUF[2]  * BUF[1];                         \
        const float du1 = BUF[4]  * BUF[6]  * BUF[5];                         \
        const float du2 = BUF[8]  * BUF[10] * BUF[9];                         \
        const float du3 = BUF[12] * BUF[14] * BUF[13];                        \
        const float uD0 = BUF[1]  * Dv;                                       \
        const float uD1 = BUF[5]  * Dv;                                       \
        const float uD2 = BUF[9]  * Dv;                                       \
        const float uD3 = BUF[13] * Dv;                                       \
        h = fmaf(e0, h, du0); float p0 = h * BUF[3];                          \
        h = fmaf(e1, h, du1); float p1 = h * BUF[7];                          \
        h = fmaf(e2, h, du2); float p2 = h * BUF[11];                         \
        h = fmaf(e3, h, du3); float p3 = h * BUF[15];                         \
        _Pragma("unroll")                                                     \
        for (int q = 0; q < 4; q++) {                                         \
            const int ln = ((PF) + q < L_SEQ) ? (PF) + q : (L_SEQ - 1);       \
            BUF[q * 4 + 0] = pdt[(size_t)ln * D_INNER];                       \
            BUF[q * 4 + 1] = pu [(size_t)ln * D_INNER];                       \
            BUF[q * 4 + 2] = pB [(size_t)ln * XDBL_W];                        \
            BUF[q * 4 + 3] = pB [(size_t)ln * XDBL_W + D_STATE];              \
        }                                                                     \
        p0 += __shfl_xor_sync(0xffffffffu, p0, 1);                            \
        p1 += __shfl_xor_sync(0xffffffffu, p1, 1);                            \
        p2 += __shfl_xor_sync(0xffffffffu, p2, 1);                            \
        p3 += __shfl_xor_sync(0xffffffffu, p3, 1);                            \
        p0 += __shfl_xor_sync(0xffffffffu, p0, 2);                            \
        p1 += __shfl_xor_sync(0xffffffffu, p1, 2);                            \
        p2 += __shfl_xor_sync(0xffffffffu, p2, 2);                            \
        p3 += __shfl_xor_sync(0xffffffffu, p3, 2);                            \
        p0 += __shfl_xor_sync(0xffffffffu, p0, 4);                            \
        p1 += __shfl_xor_sync(0xffffffffu, p1, 4);                            \
        p2 += __shfl_xor_sync(0xffffffffu, p2, 4);                            \
        p3 += __shfl_xor_sync(0xffffffffu, p3, 4);                            \
        p0 += __shfl_xor_sync(0xffffffffu, p0, 8);                            \
        p1 += __shfl_xor_sync(0xffffffffu, p1, 8);                            \
        p2 += __shfl_xor_sync(0xffffffffu, p2, 8);                            \
        p3 += __shfl_xor_sync(0xffffffffu, p3, 8);                            \
        if (n == 0) {                                                         \
            pyo[(size_t)((LB) + 0) * D_INNER] = p0 + uD0;                     \
            pyo[(size_t)((LB) + 1) * D_INNER] = p1 + uD1;                     \
            pyo[(size_t)((LB) + 2) * D_INNER] = p2 + uD2;                     \
            pyo[(size_t)((LB) + 3) * D_INNER] = p3 + uD3;                     \
        }                                                                     \
    }

    for (int l = 0; l < L_SEQ; l += 8) {
        SCAN_HALF(bA, l,     l + 8);
        SCAN_HALF(bB, l + 4, l + 12);
    }
#undef SCAN_HALF
}

// ---------------------------------------------------------------------------
__global__ void head1_kernel(const float* __restrict__ h,
                             const float* __restrict__ p1w,
                             const float* __restrict__ p1b,
                             float* __restrict__ fc)
{
    int idx = blockIdx.x * blockDim.x + threadIdx.x;
    if (idx >= B_SZ * D_FF) return;
    const int b = idx / D_FF;
    const int f = idx - b * D_FF;
    const float4* hp = (const float4*)(h + ((size_t)b * L_SEQ + (L_SEQ - 1)) * D_MODEL);
    const float4* wp = (const float4*)(p1w + (size_t)f * D_MODEL);
    float acc = 0.f;
#pragma unroll 8
    for (int k = 0; k < D_MODEL / 4; k++) {
        float4 a = hp[k], w = wp[k];
        acc += a.x * w.x + a.y * w.y + a.z * w.z + a.w * w.w;
    }
    acc += p1b[f];
    fc[idx] = 0.5f * acc * (1.f + erff(acc * 0.70710678118f));
}

__global__ void head2_kernel(const float* __restrict__ fc,
                             const float* __restrict__ p2w,
                             const float* __restrict__ p2b,
                             float* __restrict__ out)
{
    const int b = blockIdx.x;
    const int t = threadIdx.x;
    float acc = 0.f;
    for (int k = t; k < D_FF; k += 256) acc += fc[b * D_FF + k] * p2w[k];
    __shared__ float s[8];
#pragma unroll
    for (int o = 16; o; o >>= 1) acc += __shfl_xor_sync(0xffffffffu, acc, o);
    if ((t & 31) == 0) s[t >> 5] = acc;
    __syncthreads();
    if (t < 8) {
        float v = s[t];
#pragma unroll
        for (int o = 4; o; o >>= 1) v += __shfl_xor_sync(0x000000ffu, v, o);
        if (t == 0) out[b] = v + p2b[0];
    }
}

// ---------------------------------------------------------------------------
extern "C" void kernel_launch(void* const* d_in, const int* in_sizes, int n_in,
                              void* d_out, int out_size)
{
    (void)in_sizes; (void)n_in; (void)out_size;
    const float* x          = (const float*)d_in[0];
    const float* in_w       = (const float*)d_in[1];
    const float* in_b       = (const float*)d_in[2];
    const float* in_proj_w  = (const float*)d_in[3];
    const float* conv_w     = (const float*)d_in[4];
    const float* conv_b     = (const float*)d_in[5];
    const float* x_proj_w   = (const float*)d_in[6];
    const float* dt_w       = (const float*)d_in[7];
    const float* dt_b       = (const float*)d_in[8];
    const float* A_log      = (const float*)d_in[9];
    const float* D_skip     = (const float*)d_in[10];
    const float* out_proj_w = (const float*)d_in[11];
    const float* p1_w       = (const float*)d_in[12];
    const float* p1_b       = (const float*)d_in[13];
    const float* p2_w       = (const float*)d_in[14];
    const float* p2_b       = (const float*)d_in[15];
    float* out = (float*)d_out;

    float *ph, *pxz, *pxc, *pxdbl, *ppart, *pdt, *py, *pfc;
    __nv_bfloat16 *ph3, *py3, *pw3a, *pw3b;
    cudaGetSymbolAddress((void**)&ph,    g_h);
    cudaGetSymbolAddress((void**)&pxz,   g_xz);
    cudaGetSymbolAddress((void**)&pxc,   g_xc);
    cudaGetSymbolAddress((void**)&pxdbl, g_xdbl);
    cudaGetSymbolAddress((void**)&ppart, g_part);
    cudaGetSymbolAddress((void**)&pdt,   g_dt);
    cudaGetSymbolAddress((void**)&py,    g_y);
    cudaGetSymbolAddress((void**)&pfc,   g_fc);
    cudaGetSymbolAddress((void**)&ph3,   g_h3);
    cudaGetSymbolAddress((void**)&py3,   g_y3);
    cudaGetSymbolAddress((void**)&pw3a,  g_w3a);
    cudaGetSymbolAddress((void**)&pw3b,  g_w3b);

    const size_t off_a = (size_t)2 * D_INNER * 3 * D_MODEL;
    const size_t off_b = (size_t)D_MODEL * 3 * D_INNER;

    // All weight splits once (both layers each)
    split3_kernel<<<(N_LAYERS * 2 * D_INNER * D_MODEL + 255) / 256, 256>>>(
        in_proj_w, pw3a, N_LAYERS * 2 * D_INNER * D_MODEL, D_MODEL, 1);
    split3_kernel<<<(N_LAYERS * D_MODEL * D_INNER + 255) / 256, 256>>>(
        out_proj_w, pw3b, N_LAYERS * D_MODEL * D_INNER, D_INNER, 1);

    // h = x @ in_w^T + in_b  [8192,256], K=32 (FFMA); also emits h3 (split3)
    gemm_t<32, 64, 16, 4, 4, 128, 1><<<dim3(MROWS / 32, D_MODEL / 64), 128>>>(
        x, in_w, in_b, ph, ph3, D_MODEL, ENC_IN, ENC_IN, 1);

    for (int i = 0; i < N_LAYERS; i++) {
        const float* xpw = x_proj_w + (size_t)i * XDBL_W * D_INNER;
        const float* dtw = dt_w     + (size_t)i * D_INNER * DT_RANK;

        // ---- in_proj (wmma, R12 config): xz = h @ ipw^T  [8192,1024] -----
        wmma_gemm<128, 128, 64, 32, 256, 0>
            <<<dim3(MROWS / 128, (2 * D_INNER) / 128), 256>>>(
            ph3, pw3a + i * off_a, pxz, nullptr, 2 * D_INNER, 3 * D_MODEL);

        conv_silu_kernel<<<(MROWS * D_INNER / 4) / 256, 256>>>(pxz,
                conv_w + (size_t)i * D_INNER * D_CONV,
                conv_b + (size_t)i * D_INNER, pxc);

        // xdbl partials: [8192,48], K=512 split 4 (FFMA)
        gemm_t<32, 64, 16, 4, 4, 128, KSPL><<<dim3(MROWS / 32, 1, KSPL), 128>>>(
            pxc, xpw, nullptr, ppart, nullptr, XDBL_W, D_INNER, D_INNER, 0);
        reduce_part_kernel<<<(MROWS * XDBL_W / 4 + 255) / 256, 256>>>(ppart, pxdbl);

        // dt = softplus(xdbl[:, :16] @ dtw^T + dt_b) [8192,512], K=16 (FFMA)
        gemm_t<32, 64, 16, 4, 4, 128, 1><<<dim3(MROWS / 32, D_INNER / 64), 128>>>(
            pxdbl, dtw, dt_b + (size_t)i * D_INNER, pdt, nullptr,
            D_INNER, DT_RANK, XDBL_W, 2);

        // y_raw = selective scan (batched shuffle reductions)
        scan_kernel<<<(B_SZ * D_INNER / 2) * 32 / 256, 256>>>(pdt, pxc, pxdbl,
                A_log  + (size_t)i * D_INNER * D_STATE,
                D_skip + (size_t)i * D_INNER, py);

        // ---- out_proj (wmma, R12 config): h = (y*silu(z)) @ opw^T --------
        gate_split3_kernel<<<(MROWS * D_INNER / 2 + 255) / 256, 256>>>(py, pxz, py3);
        wmma_gemm<64, 128, 32, 32, 256, 1>
            <<<dim3(MROWS / 64, D_MODEL / 128), 256>>>(
            py3, pw3b + i * off_b, ph, ph3, D_MODEL, 3 * D_INNER);
    }

    head1_kernel<<<(B_SZ * D_FF) / 256, 256>>>(ph, p1_w, p1_b, pfc);
    head2_kernel<<<B_SZ, 256>>>(pfc, p2_w, p2_b, out);
}